// round 6
// baseline (speedup 1.0000x reference)
#include <cuda_runtime.h>
#include <cuda_fp16.h>
#include <cstdint>

// Problem constants
#define N_B   4
#define C_IN  256
#define H_IM  64
#define W_IM  64
#define OC    256
#define K2    9
#define OMC   27
#define HW    (H_IM*W_IM)        // 4096
#define NPIX  (N_B*HW)           // 16384
#define KDIM  (C_IN*K2)          // 2304
#define NCHK  (KDIM/32)          // 72

// ---------------- device scratch ----------------
__device__ float  g_om  [(size_t)N_B * OMC * HW];
__device__ float  g_part[(size_t)8 * N_B * OMC * HW];
__device__ __half g_colF[(size_t)KDIM * NPIX];          // fp16 im2col [kc][p]
__device__ __half g_wtB [(size_t)NCHK * 8192];          // B chunk-major, pre-swizzled

// swizzle for conflict-free ldmatrix on 64B-pitch rows
__device__ __host__ __forceinline__ uint32_t swz64(uint32_t a) {
    return a ^ (((a >> 7) & 3u) << 4);
}

// ---------------------------------------------------------------------------
// Offset conv: grid (64 ho, 4 n, 8 cg); block 256 = 4 sub x 64 wo; 32 ch/block
// ---------------------------------------------------------------------------
__global__ void offset_conv_kernel(const float* __restrict__ x,
                                   const float* __restrict__ ow)
{
    extern __shared__ float smf[];
    float* sw  = smf;                 // [32 c][27 oc][12]
    float* red = smf + 32 * 324;      // [4 sub][27 oc][64 wo]

    const int ho = blockIdx.x, n = blockIdx.y, cg = blockIdx.z;
    const int tid = threadIdx.x;
    const int wo = tid & 63, sub = tid >> 6;

    for (int idx = tid; idx < 32 * 324; idx += 256) {
        int c = idx / 324, r = idx % 324, oc = r / 12, k = r % 12;
        sw[idx] = (k < 9) ? ow[((size_t)oc * C_IN + cg * 32 + c) * 9 + k] : 0.f;
    }
    __syncthreads();

    float acc[27];
    #pragma unroll
    for (int o = 0; o < 27; o++) acc[o] = 0.f;

    #pragma unroll
    for (int i = 0; i < 8; i++) {
        int cl = sub * 8 + i;
        int c  = cg * 32 + cl;
        const float* xr = x + ((size_t)(n * C_IN + c) << 12);
        float xv[9];
        #pragma unroll
        for (int ky = 0; ky < 3; ky++) {
            int hy = ho + ky - 1;
            bool vy = (unsigned)hy < (unsigned)H_IM;
            const float* row = xr + (hy << 6);
            xv[ky*3+0] = (vy && wo >= 1)  ? row[wo-1] : 0.f;
            xv[ky*3+1] = vy               ? row[wo]   : 0.f;
            xv[ky*3+2] = (vy && wo <= 62) ? row[wo+1] : 0.f;
        }
        const float* wc = sw + cl * 324;
        #pragma unroll
        for (int o = 0; o < 27; o++) {
            float4 w0 = *reinterpret_cast<const float4*>(wc + o*12 + 0);
            float4 w1 = *reinterpret_cast<const float4*>(wc + o*12 + 4);
            float  w8 = wc[o*12 + 8];
            acc[o] += xv[0]*w0.x + xv[1]*w0.y + xv[2]*w0.z + xv[3]*w0.w
                    + xv[4]*w1.x + xv[5]*w1.y + xv[6]*w1.z + xv[7]*w1.w
                    + xv[8]*w8;
        }
    }
    #pragma unroll
    for (int o = 0; o < 27; o++) red[(sub * 27 + o) * 64 + wo] = acc[o];
    __syncthreads();

    for (int idx = tid; idx < 27 * 64; idx += 256) {
        int o = idx >> 6, w2 = idx & 63;
        float s = red[(0*27+o)*64+w2] + red[(1*27+o)*64+w2]
                + red[(2*27+o)*64+w2] + red[(3*27+o)*64+w2];
        g_part[(((size_t)cg * N_B + n) * OMC + o) * HW + (ho << 6) + w2] = s;
    }
}

__global__ void reduce_om_kernel(const float* __restrict__ ob)
{
    int idx = blockIdx.x * 256 + threadIdx.x;
    int oc = (idx >> 12) % OMC;
    size_t stride = (size_t)N_B * OMC * HW;
    float s = ob[oc];
    #pragma unroll
    for (int j = 0; j < 8; j++) s += g_part[idx + j * stride];
    g_om[idx] = s;
}

// ---------------------------------------------------------------------------
// Weight reorder: g_wtB[ch][swz(oc*64 + kcl*2)] = dcn_w[oc][c][k], fp16
// ch = k*8 + c/32, kcl = c%32
// ---------------------------------------------------------------------------
__global__ void reorder_w_kernel(const float* __restrict__ dw)
{
    int oc = blockIdx.x;
    int c  = threadIdx.x;
    #pragma unroll
    for (int k = 0; k < 9; k++) {
        float w = dw[((size_t)oc * C_IN + c) * K2 + k];
        int ch  = k * 8 + (c >> 5);
        int kcl = c & 31;
        uint32_t raw = (uint32_t)oc * 64 + kcl * 2;
        g_wtB[(size_t)ch * 8192 + (swz64(raw) >> 1)] = __float2half_rn(w);
    }
}

// ---------------------------------------------------------------------------
// Bilinear sampling -> g_colF[kc][p] fp16
// ---------------------------------------------------------------------------
__global__ void sample_kernel(const float* __restrict__ x)
{
    const int ho   = blockIdx.x;
    const int n    = blockIdx.y;
    const int half = blockIdx.z;
    const int tid  = threadIdx.x;

    __shared__ float s_w[K2][4][64];
    __shared__ int   s_idx[K2][4][64];

    for (int it = tid; it < 64 * K2; it += 256) {
        int k  = it / 64;
        int wo = it % 64;
        int p  = (ho << 6) + wo;
        const float* omn = g_om + (size_t)n * OMC * HW;

        float oy = omn[((size_t)(2*k    ) << 12) + p];
        float ox = omn[((size_t)(2*k + 1) << 12) + p];
        float mv = omn[((size_t)(18 + k ) << 12) + p];
        float m  = 1.0f / (1.0f + expf(-mv));

        float him = (float)(ho + (k / 3) - 1) + oy;
        float wim = (float)(wo + (k % 3) - 1) + ox;

        float y0 = floorf(him), x0 = floorf(wim);
        float lh = him - y0,    lw = wim - x0;
        float hh = 1.0f - lh,   hw = 1.0f - lw;
        float y1 = y0 + 1.0f,   x1 = x0 + 1.0f;

        float vy0 = (y0 >= 0.f && y0 <= 63.f) ? 1.f : 0.f;
        float vy1 = (y1 >= 0.f && y1 <= 63.f) ? 1.f : 0.f;
        float vx0 = (x0 >= 0.f && x0 <= 63.f) ? 1.f : 0.f;
        float vx1 = (x1 >= 0.f && x1 <= 63.f) ? 1.f : 0.f;

        int iy0 = (int)fminf(fmaxf(y0, 0.f), 63.f);
        int iy1 = (int)fminf(fmaxf(y1, 0.f), 63.f);
        int ix0 = (int)fminf(fmaxf(x0, 0.f), 63.f);
        int ix1 = (int)fminf(fmaxf(x1, 0.f), 63.f);

        s_w[k][0][wo] = hh * hw * m * vy0 * vx0;  s_idx[k][0][wo] = iy0 * 64 + ix0;
        s_w[k][1][wo] = hh * lw * m * vy0 * vx1;  s_idx[k][1][wo] = iy0 * 64 + ix1;
        s_w[k][2][wo] = lh * hw * m * vy1 * vx0;  s_idx[k][2][wo] = iy1 * 64 + ix0;
        s_w[k][3][wo] = lh * lw * m * vy1 * vx1;  s_idx[k][3][wo] = iy1 * 64 + ix1;
    }
    __syncthreads();

    const int wo = tid & 63;
    const int cq = tid >> 6;
    const size_t pcol = (size_t)n * HW + (ho << 6) + wo;

    float wreg[36];
    int   ireg[36];
    #pragma unroll
    for (int k = 0; k < K2; k++)
        #pragma unroll
        for (int j = 0; j < 4; j++) {
            wreg[k*4+j] = s_w[k][j][wo];
            ireg[k*4+j] = s_idx[k][j][wo];
        }

    for (int ci = 0; ci < 32; ci++) {
        int c = half * 128 + ci * 4 + cq;
        const float* xb = x + ((size_t)(n * C_IN + c) << 12);
        #pragma unroll
        for (int k = 0; k < K2; k++) {
            float v = wreg[k*4+0] * xb[ireg[k*4+0]]
                    + wreg[k*4+1] * xb[ireg[k*4+1]]
                    + wreg[k*4+2] * xb[ireg[k*4+2]]
                    + wreg[k*4+3] * xb[ireg[k*4+3]];
            g_colF[(size_t)(k * C_IN + c) * NPIX + pcol] = __float2half_rn(v);
        }
    }
}

// ---------------------------------------------------------------------------
// fp16 mma GEMM with cp.async.bulk staging + mbarrier ring.
// CTA: 128 px x 256 oc. A [32 kc][128 px] pitch 272; B [256 oc][32 kc] pitch 64
// (pre-swizzled). 512 threads = 16 warps (4M x 4N), warp tile 32x64. 3 stages.
// ---------------------------------------------------------------------------
#define APITCH   272
#define A_TILE   (32 * APITCH)          // 8704
#define B_TILE   16384
#define STAGE_SZ (A_TILE + B_TILE)      // 25088
#define NSTAGE   3
#define MBAR_OFF (NSTAGE * STAGE_SZ)    // 75264
#define GEMM_SMEM (MBAR_OFF + 64)
#define STAGE_BYTES (32 * 256 + B_TILE) // 24576

__device__ __forceinline__ void bulk_g2s(uint32_t dst, const void* src,
                                         uint32_t bytes, uint32_t mbar) {
    asm volatile(
        "cp.async.bulk.shared::cluster.global.mbarrier::complete_tx::bytes "
        "[%0], [%1], %2, [%3];"
        :: "r"(dst), "l"(src), "r"(bytes), "r"(mbar) : "memory");
}
__device__ __forceinline__ void mbar_init(uint32_t a, uint32_t c) {
    asm volatile("mbarrier.init.shared.b64 [%0], %1;" :: "r"(a), "r"(c) : "memory");
}
__device__ __forceinline__ void mbar_expect(uint32_t a, uint32_t b) {
    asm volatile("mbarrier.arrive.expect_tx.shared.b64 _, [%0], %1;" :: "r"(a), "r"(b) : "memory");
}
__device__ __forceinline__ void mbar_arrive(uint32_t a) {
    asm volatile("mbarrier.arrive.shared.b64 _, [%0];" :: "r"(a) : "memory");
}
__device__ __forceinline__ void mbar_wait(uint32_t mbar, uint32_t parity) {
    uint32_t done;
    asm volatile("{\n\t.reg .pred p;\n\t"
        "mbarrier.try_wait.parity.acquire.cta.shared::cta.b64 p, [%1], %2;\n\t"
        "selp.b32 %0, 1, 0, p;\n\t}"
        : "=r"(done) : "r"(mbar), "r"(parity) : "memory");
    if (!done) {
        asm volatile("{\n\t.reg .pred P1;\n\t"
            "W_%=:\n\t"
            "mbarrier.try_wait.parity.acquire.cta.shared::cta.b64 P1, [%0], %1, 0x989680;\n\t"
            "@P1 bra.uni D_%=;\n\t"
            "bra.uni W_%=;\n\t"
            "D_%=:\n\t}" :: "r"(mbar), "r"(parity) : "memory");
    }
}
__device__ __forceinline__ void ldmx4(uint32_t* r, uint32_t addr) {
    asm volatile("ldmatrix.sync.aligned.m8n8.x4.shared.b16 {%0,%1,%2,%3}, [%4];"
        : "=r"(r[0]), "=r"(r[1]), "=r"(r[2]), "=r"(r[3]) : "r"(addr));
}
__device__ __forceinline__ void ldmx4t(uint32_t* r, uint32_t addr) {
    asm volatile("ldmatrix.sync.aligned.m8n8.x4.trans.shared.b16 {%0,%1,%2,%3}, [%4];"
        : "=r"(r[0]), "=r"(r[1]), "=r"(r[2]), "=r"(r[3]) : "r"(addr));
}
__device__ __forceinline__ void mma_f16(float* c, const uint32_t* a, const uint32_t* b) {
    asm volatile(
        "mma.sync.aligned.m16n8k16.row.col.f32.f16.f16.f32 "
        "{%0,%1,%2,%3}, {%4,%5,%6,%7}, {%8,%9}, {%0,%1,%2,%3};"
        : "+f"(c[0]), "+f"(c[1]), "+f"(c[2]), "+f"(c[3])
        : "r"(a[0]), "r"(a[1]), "r"(a[2]), "r"(a[3]), "r"(b[0]), "r"(b[1]));
}

__global__ void __launch_bounds__(512, 1) gemm_bulk_kernel(float* __restrict__ out)
{
    extern __shared__ char sm[];
    const uint32_t sb = (uint32_t)__cvta_generic_to_shared(sm);
    const int tid = threadIdx.x;
    const int wid = tid >> 5, lid = tid & 31;
    const int warpM = wid & 3, warpN = wid >> 2;
    const int bm0 = blockIdx.x * 128;

    // mbarriers: full[s] = MBAR_OFF + s*16, empty[s] = +8
    if (tid == 0) {
        #pragma unroll
        for (int s = 0; s < NSTAGE; s++) {
            mbar_init(sb + MBAR_OFF + s*16, 1);
            mbar_init(sb + MBAR_OFF + s*16 + 8, 512);
        }
    }
    __syncthreads();

    float acc[2][8][4];
    #pragma unroll
    for (int i = 0; i < 2; i++)
        #pragma unroll
        for (int j = 0; j < 8; j++)
            #pragma unroll
            for (int q = 0; q < 4; q++) acc[i][j][q] = 0.f;

    auto fill = [&](int f) {
        int s = f % NSTAGE;
        uint32_t base = sb + s * STAGE_SZ;
        uint32_t mb   = sb + MBAR_OFF + s * 16;
        if (lid == 0) mbar_expect(mb, STAGE_BYTES);
        __syncwarp();
        // 32 A-row copies (one per lane)
        bulk_g2s(base + lid * APITCH,
                 g_colF + (size_t)(f * 32 + lid) * NPIX + bm0, 256, mb);
        // one B copy
        if (lid == 0)
            bulk_g2s(base + A_TILE, g_wtB + (size_t)f * 8192, B_TILE, mb);
    };

    if (wid == 0) { fill(0); fill(1); }

    // ldmatrix A per-thread address base
    const int qq = lid >> 3;
    const int jr = lid & 7;
    const uint32_t aoff = (uint32_t)(((qq >> 1) * 8 + jr) * APITCH
                                     + (warpM * 32 + (qq & 1) * 8) * 2);
    const int oc_lane = warpN * 64 + (qq >> 1) * 8 + jr;   // + pi*16

    for (int ch = 0; ch < NCHK; ch++) {
        if (wid == 0) {
            int f = ch + 2;
            if (f < NCHK) {
                if (f >= NSTAGE)
                    mbar_wait(sb + MBAR_OFF + (f % NSTAGE) * 16 + 8,
                              ((f / NSTAGE) - 1) & 1);
                fill(f);
            }
        }
        const int s = ch % NSTAGE;
        mbar_wait(sb + MBAR_OFF + s * 16, (ch / NSTAGE) & 1);

        const uint32_t ab = sb + s * STAGE_SZ;
        const uint32_t bb = ab + A_TILE;

        #pragma unroll
        for (int kp = 0; kp < 2; kp++) {
            uint32_t Af[2][4], Bf[4][4];
            #pragma unroll
            for (int mi = 0; mi < 2; mi++)
                ldmx4t(Af[mi], ab + aoff + kp * (16 * APITCH) + mi * 32);
            #pragma unroll
            for (int pi = 0; pi < 4; pi++) {
                uint32_t raw = (uint32_t)(oc_lane + pi * 16) * 64
                             + (kp * 2 + (qq & 1)) * 16;
                ldmx4(Bf[pi], bb + swz64(raw));
            }
            #pragma unroll
            for (int mi = 0; mi < 2; mi++)
                #pragma unroll
                for (int pi = 0; pi < 4; pi++) {
                    mma_f16(acc[mi][pi*2],   Af[mi], &Bf[pi][0]);
                    mma_f16(acc[mi][pi*2+1], Af[mi], &Bf[pi][2]);
                }
        }
        mbar_arrive(sb + MBAR_OFF + s * 16 + 8);
    }

    // epilogue
    const int nIdx = bm0 >> 12;
    const int hwb  = bm0 & 4095;
    #pragma unroll
    for (int mi = 0; mi < 2; mi++) {
        int r = hwb + warpM * 32 + mi * 16 + (lid >> 2);
        #pragma unroll
        for (int jj = 0; jj < 8; jj++) {
            int oc = warpN * 64 + jj * 8 + (lid & 3) * 2;
            size_t base = ((size_t)(nIdx * OC + oc) << 12);
            out[base + r]            = acc[mi][jj][0];
            out[base + 4096 + r]     = acc[mi][jj][1];
            out[base + r + 8]        = acc[mi][jj][2];
            out[base + 4096 + r + 8] = acc[mi][jj][3];
        }
    }
}

// ---------------------------------------------------------------------------
extern "C" void kernel_launch(void* const* d_in, const int* in_sizes, int n_in,
                              void* d_out, int out_size)
{
    const float* x  = (const float*)d_in[0];
    const float* ow = (const float*)d_in[1];
    const float* ob = (const float*)d_in[2];
    const float* dw = (const float*)d_in[3];
    float* out = (float*)d_out;

    const int conv_smem = 32*324*4 + 4*27*64*4;   // 69120
    cudaFuncSetAttribute(offset_conv_kernel,
        cudaFuncAttributeMaxDynamicSharedMemorySize, conv_smem);
    cudaFuncSetAttribute(gemm_bulk_kernel,
        cudaFuncAttributeMaxDynamicSharedMemorySize, GEMM_SMEM);

    offset_conv_kernel<<<dim3(H_IM, N_B, 8), 256, conv_smem>>>(x, ow);
    reduce_om_kernel<<<(N_B*OMC*HW)/256, 256>>>(ob);
    reorder_w_kernel<<<OC, C_IN>>>(dw);
    sample_kernel<<<dim3(H_IM, N_B, 2), 256>>>(x);
    gemm_bulk_kernel<<<NPIX/128, 512, GEMM_SMEM>>>(out);
}

// round 7
// speedup vs baseline: 1.2586x; 1.2586x over previous
#include <cuda_runtime.h>
#include <cuda_fp16.h>
#include <cstdint>

// Problem constants
#define N_B   4
#define C_IN  256
#define H_IM  64
#define W_IM  64
#define OC    256
#define K2    9
#define OMC   27
#define HW    (H_IM*W_IM)        // 4096
#define NPIX  (N_B*HW)           // 16384
#define KDIM  (C_IN*K2)          // 2304
#define NCHK  (KDIM/32)          // 72

// ---------------- device scratch ----------------
__device__ float  g_om  [(size_t)N_B * OMC * HW];
__device__ __half g_colF[(size_t)KDIM * NPIX];          // fp16 im2col [kc][p]
__device__ __half g_wtB [(size_t)NCHK * 8192];          // dcn weights, chunk-major, pre-swizzled
__device__ __half g_owB [(size_t)NCHK * 1024];          // offset weights [ch][32oc x 32kc], pre-swizzled

// swizzle for conflict-free ldmatrix on 64B-pitch rows
__device__ __host__ __forceinline__ uint32_t swz64(uint32_t a) {
    return a ^ (((a >> 7) & 3u) << 4);
}

__device__ __forceinline__ void sts16(uint32_t addr, unsigned short v) {
    asm volatile("st.shared.u16 [%0], %1;" :: "r"(addr), "h"(v));
}
__device__ __forceinline__ void ldmx4(uint32_t* r, uint32_t addr) {
    asm volatile("ldmatrix.sync.aligned.m8n8.x4.shared.b16 {%0,%1,%2,%3}, [%4];"
        : "=r"(r[0]), "=r"(r[1]), "=r"(r[2]), "=r"(r[3]) : "r"(addr));
}
__device__ __forceinline__ void ldmx4t(uint32_t* r, uint32_t addr) {
    asm volatile("ldmatrix.sync.aligned.m8n8.x4.trans.shared.b16 {%0,%1,%2,%3}, [%4];"
        : "=r"(r[0]), "=r"(r[1]), "=r"(r[2]), "=r"(r[3]) : "r"(addr));
}
__device__ __forceinline__ void mma_f16(float* c, const uint32_t* a, const uint32_t* b) {
    asm volatile(
        "mma.sync.aligned.m16n8k16.row.col.f32.f16.f16.f32 "
        "{%0,%1,%2,%3}, {%4,%5,%6,%7}, {%8,%9}, {%0,%1,%2,%3};"
        : "+f"(c[0]), "+f"(c[1]), "+f"(c[2]), "+f"(c[3])
        : "r"(a[0]), "r"(a[1]), "r"(a[2]), "r"(a[3]), "r"(b[0]), "r"(b[1]));
}

// ---------------------------------------------------------------------------
// Prep: pack both weight tensors (fp16, chunk-major, pre-swizzled).
// blocks [0,256): dcn_w -> g_wtB ; blocks [256,328): offset_w -> g_owB
// ---------------------------------------------------------------------------
__global__ void prep_kernel(const float* __restrict__ dw,
                            const float* __restrict__ ow)
{
    if (blockIdx.x < 256) {
        int oc = blockIdx.x;
        int c  = threadIdx.x;
        #pragma unroll
        for (int k = 0; k < 9; k++) {
            float w = dw[((size_t)oc * C_IN + c) * K2 + k];
            int ch  = k * 8 + (c >> 5);
            int kcl = c & 31;
            uint32_t raw = (uint32_t)oc * 64 + kcl * 2;
            g_wtB[(size_t)ch * 8192 + (swz64(raw) >> 1)] = __float2half_rn(w);
        }
    } else {
        int ch = blockIdx.x - 256;
        int k  = ch >> 3;
        int c0 = (ch & 7) * 32;
        #pragma unroll
        for (int it = 0; it < 4; it++) {
            int idx = threadIdx.x + it * 256;        // 0..1023
            int oc = idx >> 5, kcl = idx & 31;
            float w = (oc < OMC)
                ? ow[((size_t)oc * C_IN + c0 + kcl) * K2 + k] : 0.f;
            uint32_t raw = (uint32_t)oc * 64 + kcl * 2;
            g_owB[(size_t)ch * 1024 + (swz64(raw) >> 1)] = __float2half_rn(w);
        }
    }
}

// ---------------------------------------------------------------------------
// Offset conv as fp16 implicit GEMM: om[128 px][27 oc] per CTA.
// A tile [32 kc][128 px] built from shifted x (coalesced), B = g_owB chunk.
// 256 threads = 8 warps, each warp 16 px x 32 oc. Double-buffered.
// Writes g_om[n][o][hw] WITH bias.
// ---------------------------------------------------------------------------
#define CV_APITCH 272
#define CV_A_SZ   (32 * CV_APITCH)     // 8704
#define CV_B_SZ   2048
#define CV_STG    (CV_A_SZ + CV_B_SZ)  // 10752

__global__ void __launch_bounds__(256, 1) conv_gemm_kernel(
    const float* __restrict__ x, const float* __restrict__ ob)
{
    __shared__ char sm[2 * CV_STG];
    const uint32_t sb = (uint32_t)__cvta_generic_to_shared(sm);
    const int tid = threadIdx.x;
    const int wid = tid >> 5, lid = tid & 31;
    const int bm0 = blockIdx.x * 128;
    const int nIdx = bm0 >> 12, hwb = bm0 & 4095, ho0 = hwb >> 6;
    const float* xn = x + ((size_t)nIdx * C_IN << 12);

    // build constants (p fixed per thread)
    const int p = tid & 127;
    const int kcl0 = tid >> 7;          // 0 or 1
    const int pho = p >> 6, pwo = p & 63;

    float acc[4][4];
    #pragma unroll
    for (int j = 0; j < 4; j++)
        #pragma unroll
        for (int q = 0; q < 4; q++) acc[j][q] = 0.f;

    auto build = [&](int ch, int st) {
        const int k = ch >> 3, c0 = (ch & 7) * 32;
        const int dy = k / 3 - 1, dx = k % 3 - 1;
        const int hy = ho0 + pho + dy;
        const int wx = pwo + dx;
        const bool v = ((unsigned)hy < 64u) && ((unsigned)wx < 64u);
        const float* src = xn + ((size_t)(c0 + kcl0) << 12) + (hy << 6) + wx;
        const uint32_t dst = sb + st * CV_STG + kcl0 * CV_APITCH + p * 2;
        #pragma unroll
        for (int it = 0; it < 16; it++) {
            float val = 0.f;
            if (v) val = src[(size_t)(it * 2) << 12];
            sts16(dst + it * 2 * CV_APITCH,
                  __half_as_ushort(__float2half_rn(val)));
        }
        if (tid < 128) {
            const uint4* bsrc = (const uint4*)(g_owB + (size_t)ch * 1024);
            *(uint4*)(sm + st * CV_STG + CV_A_SZ + tid * 16) = bsrc[tid];
        }
    };

    const int qq = lid >> 3, jr = lid & 7;
    const uint32_t aoff = (uint32_t)(((qq >> 1) * 8 + jr) * CV_APITCH
                                     + (wid * 16 + (qq & 1) * 8) * 2);
    const int oc_l = (qq >> 1) * 8 + jr;

    build(0, 0);
    __syncthreads();

    for (int ch = 0; ch < NCHK; ch++) {
        const int st = ch & 1;
        if (ch + 1 < NCHK) build(ch + 1, st ^ 1);

        const uint32_t ab = sb + st * CV_STG;
        const uint32_t bb = ab + CV_A_SZ;
        #pragma unroll
        for (int kp = 0; kp < 2; kp++) {
            uint32_t Af[4];
            ldmx4t(Af, ab + aoff + kp * (16 * CV_APITCH));
            #pragma unroll
            for (int pi = 0; pi < 2; pi++) {
                uint32_t Bf[4];
                uint32_t raw = (uint32_t)(oc_l + pi * 16) * 64
                             + (kp * 2 + (qq & 1)) * 16;
                ldmx4(Bf, bb + swz64(raw));
                mma_f16(acc[pi*2],   Af, &Bf[0]);
                mma_f16(acc[pi*2+1], Af, &Bf[2]);
            }
        }
        __syncthreads();
    }

    // epilogue: smem transpose -> coalesced g_om stores (+bias)
    float* T = (float*)sm;               // [32][136]
    const int r0 = wid * 16 + (lid >> 2);
    #pragma unroll
    for (int jj = 0; jj < 4; jj++) {
        int oc = jj * 8 + (lid & 3) * 2;
        T[ oc      * 136 + r0    ] = acc[jj][0];
        T[(oc + 1) * 136 + r0    ] = acc[jj][1];
        T[ oc      * 136 + r0 + 8] = acc[jj][2];
        T[(oc + 1) * 136 + r0 + 8] = acc[jj][3];
    }
    __syncthreads();
    for (int idx = tid; idx < OMC * 128; idx += 256) {
        int o = idx >> 7, m = idx & 127;
        g_om[((size_t)(nIdx * OMC + o) << 12) + hwb + m] = T[o * 136 + m] + ob[o];
    }
}

// ---------------------------------------------------------------------------
// Bilinear sampling -> g_colF[kc][p] fp16 (occupancy-restructured)
// ---------------------------------------------------------------------------
__global__ void __launch_bounds__(256, 4) sample_kernel(const float* __restrict__ x)
{
    const int ho   = blockIdx.x;
    const int n    = blockIdx.y;
    const int half = blockIdx.z;
    const int tid  = threadIdx.x;

    __shared__ float s_w[K2][4][64];
    __shared__ int   s_idx[K2][4][64];

    for (int it = tid; it < 64 * K2; it += 256) {
        int k  = it / 64;
        int wo = it % 64;
        int p  = (ho << 6) + wo;
        const float* omn = g_om + (size_t)n * OMC * HW;

        float oy = omn[((size_t)(2*k    ) << 12) + p];
        float ox = omn[((size_t)(2*k + 1) << 12) + p];
        float mv = omn[((size_t)(18 + k ) << 12) + p];
        float m  = 1.0f / (1.0f + expf(-mv));

        float him = (float)(ho + (k / 3) - 1) + oy;
        float wim = (float)(wo + (k % 3) - 1) + ox;

        float y0 = floorf(him), x0 = floorf(wim);
        float lh = him - y0,    lw = wim - x0;
        float hh = 1.0f - lh,   hw = 1.0f - lw;
        float y1 = y0 + 1.0f,   x1 = x0 + 1.0f;

        float vy0 = (y0 >= 0.f && y0 <= 63.f) ? 1.f : 0.f;
        float vy1 = (y1 >= 0.f && y1 <= 63.f) ? 1.f : 0.f;
        float vx0 = (x0 >= 0.f && x0 <= 63.f) ? 1.f : 0.f;
        float vx1 = (x1 >= 0.f && x1 <= 63.f) ? 1.f : 0.f;

        int iy0 = (int)fminf(fmaxf(y0, 0.f), 63.f);
        int iy1 = (int)fminf(fmaxf(y1, 0.f), 63.f);
        int ix0 = (int)fminf(fmaxf(x0, 0.f), 63.f);
        int ix1 = (int)fminf(fmaxf(x1, 0.f), 63.f);

        s_w[k][0][wo] = hh * hw * m * vy0 * vx0;  s_idx[k][0][wo] = iy0 * 64 + ix0;
        s_w[k][1][wo] = hh * lw * m * vy0 * vx1;  s_idx[k][1][wo] = iy0 * 64 + ix1;
        s_w[k][2][wo] = lh * hw * m * vy1 * vx0;  s_idx[k][2][wo] = iy1 * 64 + ix0;
        s_w[k][3][wo] = lh * lw * m * vy1 * vx1;  s_idx[k][3][wo] = iy1 * 64 + ix1;
    }
    __syncthreads();

    const int wo = tid & 63;
    const int cq = tid >> 6;
    const size_t pcol = (size_t)n * HW + (ho << 6) + wo;
    const float* xnn = x + (((size_t)(n * C_IN) + half * 128 + cq) << 12);
    __half* dstBase = g_colF + (size_t)(half * 128 + cq) * NPIX + pcol;

    #pragma unroll
    for (int k = 0; k < K2; k++) {
        float w0 = s_w[k][0][wo], w1 = s_w[k][1][wo];
        float w2 = s_w[k][2][wo], w3 = s_w[k][3][wo];
        int i0 = s_idx[k][0][wo], i1 = s_idx[k][1][wo];
        int i2 = s_idx[k][2][wo], i3 = s_idx[k][3][wo];
        __half* dst = dstBase + (size_t)k * C_IN * NPIX;
        const float* xb = xnn;
        #pragma unroll 4
        for (int ci = 0; ci < 32; ci++) {
            float v = w0 * xb[i0] + w1 * xb[i1] + w2 * xb[i2] + w3 * xb[i3];
            dst[(size_t)ci * 4 * NPIX] = __float2half_rn(v);
            xb += 4 * HW;
        }
    }
}

// ---------------------------------------------------------------------------
// fp16 mma GEMM with cp.async.bulk staging + mbarrier ring (unchanged from R6)
// ---------------------------------------------------------------------------
#define APITCH   272
#define A_TILE   (32 * APITCH)
#define B_TILE   16384
#define STAGE_SZ (A_TILE + B_TILE)
#define NSTAGE   3
#define MBAR_OFF (NSTAGE * STAGE_SZ)
#define GEMM_SMEM (MBAR_OFF + 64)
#define STAGE_BYTES (32 * 256 + B_TILE)

__device__ __forceinline__ void bulk_g2s(uint32_t dst, const void* src,
                                         uint32_t bytes, uint32_t mbar) {
    asm volatile(
        "cp.async.bulk.shared::cluster.global.mbarrier::complete_tx::bytes "
        "[%0], [%1], %2, [%3];"
        :: "r"(dst), "l"(src), "r"(bytes), "r"(mbar) : "memory");
}
__device__ __forceinline__ void mbar_init(uint32_t a, uint32_t c) {
    asm volatile("mbarrier.init.shared.b64 [%0], %1;" :: "r"(a), "r"(c) : "memory");
}
__device__ __forceinline__ void mbar_expect(uint32_t a, uint32_t b) {
    asm volatile("mbarrier.arrive.expect_tx.shared.b64 _, [%0], %1;" :: "r"(a), "r"(b) : "memory");
}
__device__ __forceinline__ void mbar_arrive(uint32_t a) {
    asm volatile("mbarrier.arrive.shared.b64 _, [%0];" :: "r"(a) : "memory");
}
__device__ __forceinline__ void mbar_wait(uint32_t mbar, uint32_t parity) {
    uint32_t done;
    asm volatile("{\n\t.reg .pred p;\n\t"
        "mbarrier.try_wait.parity.acquire.cta.shared::cta.b64 p, [%1], %2;\n\t"
        "selp.b32 %0, 1, 0, p;\n\t}"
        : "=r"(done) : "r"(mbar), "r"(parity) : "memory");
    if (!done) {
        asm volatile("{\n\t.reg .pred P1;\n\t"
            "W_%=:\n\t"
            "mbarrier.try_wait.parity.acquire.cta.shared::cta.b64 P1, [%0], %1, 0x989680;\n\t"
            "@P1 bra.uni D_%=;\n\t"
            "bra.uni W_%=;\n\t"
            "D_%=:\n\t}" :: "r"(mbar), "r"(parity) : "memory");
    }
}

__global__ void __launch_bounds__(512, 1) gemm_bulk_kernel(float* __restrict__ out)
{
    extern __shared__ char sm[];
    const uint32_t sb = (uint32_t)__cvta_generic_to_shared(sm);
    const int tid = threadIdx.x;
    const int wid = tid >> 5, lid = tid & 31;
    const int warpM = wid & 3, warpN = wid >> 2;
    const int bm0 = blockIdx.x * 128;

    if (tid == 0) {
        #pragma unroll
        for (int s = 0; s < NSTAGE; s++) {
            mbar_init(sb + MBAR_OFF + s*16, 1);
            mbar_init(sb + MBAR_OFF + s*16 + 8, 512);
        }
    }
    __syncthreads();

    float acc[2][8][4];
    #pragma unroll
    for (int i = 0; i < 2; i++)
        #pragma unroll
        for (int j = 0; j < 8; j++)
            #pragma unroll
            for (int q = 0; q < 4; q++) acc[i][j][q] = 0.f;

    auto fill = [&](int f) {
        int s = f % NSTAGE;
        uint32_t base = sb + s * STAGE_SZ;
        uint32_t mb   = sb + MBAR_OFF + s * 16;
        if (lid == 0) mbar_expect(mb, STAGE_BYTES);
        __syncwarp();
        bulk_g2s(base + lid * APITCH,
                 g_colF + (size_t)(f * 32 + lid) * NPIX + bm0, 256, mb);
        if (lid == 0)
            bulk_g2s(base + A_TILE, g_wtB + (size_t)f * 8192, B_TILE, mb);
    };

    if (wid == 0) { fill(0); fill(1); }

    const int qq = lid >> 3;
    const int jr = lid & 7;
    const uint32_t aoff = (uint32_t)(((qq >> 1) * 8 + jr) * APITCH
                                     + (warpM * 32 + (qq & 1) * 8) * 2);
    const int oc_lane = warpN * 64 + (qq >> 1) * 8 + jr;

    for (int ch = 0; ch < NCHK; ch++) {
        if (wid == 0) {
            int f = ch + 2;
            if (f < NCHK) {
                if (f >= NSTAGE)
                    mbar_wait(sb + MBAR_OFF + (f % NSTAGE) * 16 + 8,
                              ((f / NSTAGE) - 1) & 1);
                fill(f);
            }
        }
        const int s = ch % NSTAGE;
        mbar_wait(sb + MBAR_OFF + s * 16, (ch / NSTAGE) & 1);

        const uint32_t ab = sb + s * STAGE_SZ;
        const uint32_t bb = ab + A_TILE;

        #pragma unroll
        for (int kp = 0; kp < 2; kp++) {
            uint32_t Af[2][4], Bf[4][4];
            #pragma unroll
            for (int mi = 0; mi < 2; mi++)
                ldmx4t(Af[mi], ab + aoff + kp * (16 * APITCH) + mi * 32);
            #pragma unroll
            for (int pi = 0; pi < 4; pi++) {
                uint32_t raw = (uint32_t)(oc_lane + pi * 16) * 64
                             + (kp * 2 + (qq & 1)) * 16;
                ldmx4(Bf[pi], bb + swz64(raw));
            }
            #pragma unroll
            for (int mi = 0; mi < 2; mi++)
                #pragma unroll
                for (int pi = 0; pi < 4; pi++) {
                    mma_f16(acc[mi][pi*2],   Af[mi], &Bf[pi][0]);
                    mma_f16(acc[mi][pi*2+1], Af[mi], &Bf[pi][2]);
                }
        }
        mbar_arrive(sb + MBAR_OFF + s * 16 + 8);
    }

    const int nIdx = bm0 >> 12;
    const int hwb  = bm0 & 4095;
    #pragma unroll
    for (int mi = 0; mi < 2; mi++) {
        int r = hwb + warpM * 32 + mi * 16 + (lid >> 2);
        #pragma unroll
        for (int jj = 0; jj < 8; jj++) {
            int oc = warpN * 64 + jj * 8 + (lid & 3) * 2;
            size_t base = ((size_t)(nIdx * OC + oc) << 12);
            out[base + r]            = acc[mi][jj][0];
            out[base + 4096 + r]     = acc[mi][jj][1];
            out[base + r + 8]        = acc[mi][jj][2];
            out[base + 4096 + r + 8] = acc[mi][jj][3];
        }
    }
}

// ---------------------------------------------------------------------------
extern "C" void kernel_launch(void* const* d_in, const int* in_sizes, int n_in,
                              void* d_out, int out_size)
{
    const float* x  = (const float*)d_in[0];
    const float* ow = (const float*)d_in[1];
    const float* ob = (const float*)d_in[2];
    const float* dw = (const float*)d_in[3];
    float* out = (float*)d_out;

    cudaFuncSetAttribute(gemm_bulk_kernel,
        cudaFuncAttributeMaxDynamicSharedMemorySize, GEMM_SMEM);

    prep_kernel<<<256 + NCHK, 256>>>(dw, ow);
    conv_gemm_kernel<<<NPIX/128, 256>>>(x, ob);
    sample_kernel<<<dim3(H_IM, N_B, 2), 256>>>(x);
    gemm_bulk_kernel<<<NPIX/128, 512, GEMM_SMEM>>>(out);
}

// round 8
// speedup vs baseline: 1.6344x; 1.2986x over previous
#include <cuda_runtime.h>
#include <cuda_fp16.h>
#include <cstdint>

// Problem constants
#define N_B   4
#define C_IN  256
#define H_IM  64
#define W_IM  64
#define OC    256
#define K2    9
#define OMC   27
#define HW    (H_IM*W_IM)        // 4096
#define NPIX  (N_B*HW)           // 16384
#define KDIM  (C_IN*K2)          // 2304
#define NCHK  (KDIM/32)          // 72
#define NTILE (NPIX/128)         // 128

// ---------------- device scratch ----------------
__device__ float  g_om  [(size_t)N_B * OMC * HW];
__device__ __half g_colA[(size_t)NTILE * NCHK * 4096];  // tiled im2col: [tile][ch][32x128], swizzled
__device__ __half g_wtB [(size_t)NCHK * 8192];          // dcn weights, chunk-major, pre-swizzled
__device__ __half g_owB [(size_t)NCHK * 1024];          // offset weights, pre-swizzled

// swizzle for conflict-free ldmatrix on 64B-pitch rows (B tiles)
__device__ __host__ __forceinline__ uint32_t swz64(uint32_t a) {
    return a ^ (((a >> 7) & 3u) << 4);
}
// swizzle for conflict-free ldmatrix.trans on 256B-pitch rows (A tiles)
__device__ __host__ __forceinline__ uint32_t swzA(uint32_t a) {
    return a ^ (((a >> 8) & 7u) << 4);
}

__device__ __forceinline__ void sts16(uint32_t addr, unsigned short v) {
    asm volatile("st.shared.u16 [%0], %1;" :: "r"(addr), "h"(v));
}
__device__ __forceinline__ void ldmx4(uint32_t* r, uint32_t addr) {
    asm volatile("ldmatrix.sync.aligned.m8n8.x4.shared.b16 {%0,%1,%2,%3}, [%4];"
        : "=r"(r[0]), "=r"(r[1]), "=r"(r[2]), "=r"(r[3]) : "r"(addr));
}
__device__ __forceinline__ void ldmx4t(uint32_t* r, uint32_t addr) {
    asm volatile("ldmatrix.sync.aligned.m8n8.x4.trans.shared.b16 {%0,%1,%2,%3}, [%4];"
        : "=r"(r[0]), "=r"(r[1]), "=r"(r[2]), "=r"(r[3]) : "r"(addr));
}
__device__ __forceinline__ void mma_f16(float* c, const uint32_t* a, const uint32_t* b) {
    asm volatile(
        "mma.sync.aligned.m16n8k16.row.col.f32.f16.f16.f32 "
        "{%0,%1,%2,%3}, {%4,%5,%6,%7}, {%8,%9}, {%0,%1,%2,%3};"
        : "+f"(c[0]), "+f"(c[1]), "+f"(c[2]), "+f"(c[3])
        : "r"(a[0]), "r"(a[1]), "r"(a[2]), "r"(a[3]), "r"(b[0]), "r"(b[1]));
}

// ---------------------------------------------------------------------------
// Prep: pack both weight tensors (fp16, chunk-major, pre-swizzled).
// ---------------------------------------------------------------------------
__global__ void prep_kernel(const float* __restrict__ dw,
                            const float* __restrict__ ow)
{
    if (blockIdx.x < 256) {
        int oc = blockIdx.x;
        int c  = threadIdx.x;
        #pragma unroll
        for (int k = 0; k < 9; k++) {
            float w = dw[((size_t)oc * C_IN + c) * K2 + k];
            int ch  = k * 8 + (c >> 5);
            int kcl = c & 31;
            uint32_t raw = (uint32_t)oc * 64 + kcl * 2;
            g_wtB[(size_t)ch * 8192 + (swz64(raw) >> 1)] = __float2half_rn(w);
        }
    } else {
        int ch = blockIdx.x - 256;
        int k  = ch >> 3;
        int c0 = (ch & 7) * 32;
        #pragma unroll
        for (int it = 0; it < 4; it++) {
            int idx = threadIdx.x + it * 256;
            int oc = idx >> 5, kcl = idx & 31;
            float w = (oc < OMC)
                ? ow[((size_t)oc * C_IN + c0 + kcl) * K2 + k] : 0.f;
            uint32_t raw = (uint32_t)oc * 64 + kcl * 2;
            g_owB[(size_t)ch * 1024 + (swz64(raw) >> 1)] = __float2half_rn(w);
        }
    }
}

// ---------------------------------------------------------------------------
// Offset conv as fp16 implicit GEMM (unchanged from R7)
// ---------------------------------------------------------------------------
#define CV_APITCH 272
#define CV_A_SZ   (32 * CV_APITCH)
#define CV_B_SZ   2048
#define CV_STG    (CV_A_SZ + CV_B_SZ)

__global__ void __launch_bounds__(256, 1) conv_gemm_kernel(
    const float* __restrict__ x, const float* __restrict__ ob)
{
    __shared__ char sm[2 * CV_STG];
    const uint32_t sb = (uint32_t)__cvta_generic_to_shared(sm);
    const int tid = threadIdx.x;
    const int wid = tid >> 5, lid = tid & 31;
    const int bm0 = blockIdx.x * 128;
    const int nIdx = bm0 >> 12, hwb = bm0 & 4095, ho0 = hwb >> 6;
    const float* xn = x + ((size_t)nIdx * C_IN << 12);

    const int p = tid & 127;
    const int kcl0 = tid >> 7;
    const int pho = p >> 6, pwo = p & 63;

    float acc[4][4];
    #pragma unroll
    for (int j = 0; j < 4; j++)
        #pragma unroll
        for (int q = 0; q < 4; q++) acc[j][q] = 0.f;

    auto build = [&](int ch, int st) {
        const int k = ch >> 3, c0 = (ch & 7) * 32;
        const int dy = k / 3 - 1, dx = k % 3 - 1;
        const int hy = ho0 + pho + dy;
        const int wx = pwo + dx;
        const bool v = ((unsigned)hy < 64u) && ((unsigned)wx < 64u);
        const float* src = xn + ((size_t)(c0 + kcl0) << 12) + (hy << 6) + wx;
        const uint32_t dst = sb + st * CV_STG + kcl0 * CV_APITCH + p * 2;
        #pragma unroll
        for (int it = 0; it < 16; it++) {
            float val = 0.f;
            if (v) val = src[(size_t)(it * 2) << 12];
            sts16(dst + it * 2 * CV_APITCH,
                  __half_as_ushort(__float2half_rn(val)));
        }
        if (tid < 128) {
            const uint4* bsrc = (const uint4*)(g_owB + (size_t)ch * 1024);
            *(uint4*)(sm + st * CV_STG + CV_A_SZ + tid * 16) = bsrc[tid];
        }
    };

    const int qq = lid >> 3, jr = lid & 7;
    const uint32_t aoff = (uint32_t)(((qq >> 1) * 8 + jr) * CV_APITCH
                                     + (wid * 16 + (qq & 1) * 8) * 2);
    const int oc_l = (qq >> 1) * 8 + jr;

    build(0, 0);
    __syncthreads();

    for (int ch = 0; ch < NCHK; ch++) {
        const int st = ch & 1;
        if (ch + 1 < NCHK) build(ch + 1, st ^ 1);

        const uint32_t ab = sb + st * CV_STG;
        const uint32_t bb = ab + CV_A_SZ;
        #pragma unroll
        for (int kp = 0; kp < 2; kp++) {
            uint32_t Af[4];
            ldmx4t(Af, ab + aoff + kp * (16 * CV_APITCH));
            #pragma unroll
            for (int pi = 0; pi < 2; pi++) {
                uint32_t Bf[4];
                uint32_t raw = (uint32_t)(oc_l + pi * 16) * 64
                             + (kp * 2 + (qq & 1)) * 16;
                ldmx4(Bf, bb + swz64(raw));
                mma_f16(acc[pi*2],   Af, &Bf[0]);
                mma_f16(acc[pi*2+1], Af, &Bf[2]);
            }
        }
        __syncthreads();
    }

    float* T = (float*)sm;
    const int r0 = wid * 16 + (lid >> 2);
    #pragma unroll
    for (int jj = 0; jj < 4; jj++) {
        int oc = jj * 8 + (lid & 3) * 2;
        T[ oc      * 136 + r0    ] = acc[jj][0];
        T[(oc + 1) * 136 + r0    ] = acc[jj][1];
        T[ oc      * 136 + r0 + 8] = acc[jj][2];
        T[(oc + 1) * 136 + r0 + 8] = acc[jj][3];
    }
    __syncthreads();
    for (int idx = tid; idx < OMC * 128; idx += 256) {
        int o = idx >> 7, m = idx & 127;
        g_om[((size_t)(nIdx * OMC + o) << 12) + hwb + m] = T[o * 136 + m] + ob[o];
    }
}

// ---------------------------------------------------------------------------
// Bilinear sampling -> tiled/swizzled g_colA
// ---------------------------------------------------------------------------
__global__ void __launch_bounds__(256, 4) sample_kernel(const float* __restrict__ x)
{
    const int ho   = blockIdx.x;
    const int n    = blockIdx.y;
    const int half = blockIdx.z;
    const int tid  = threadIdx.x;

    __shared__ float s_w[K2][4][64];
    __shared__ int   s_idx[K2][4][64];

    for (int it = tid; it < 64 * K2; it += 256) {
        int k  = it / 64;
        int wo = it % 64;
        int p  = (ho << 6) + wo;
        const float* omn = g_om + (size_t)n * OMC * HW;

        float oy = omn[((size_t)(2*k    ) << 12) + p];
        float ox = omn[((size_t)(2*k + 1) << 12) + p];
        float mv = omn[((size_t)(18 + k ) << 12) + p];
        float m  = 1.0f / (1.0f + expf(-mv));

        float him = (float)(ho + (k / 3) - 1) + oy;
        float wim = (float)(wo + (k % 3) - 1) + ox;

        float y0 = floorf(him), x0 = floorf(wim);
        float lh = him - y0,    lw = wim - x0;
        float hh = 1.0f - lh,   hw = 1.0f - lw;
        float y1 = y0 + 1.0f,   x1 = x0 + 1.0f;

        float vy0 = (y0 >= 0.f && y0 <= 63.f) ? 1.f : 0.f;
        float vy1 = (y1 >= 0.f && y1 <= 63.f) ? 1.f : 0.f;
        float vx0 = (x0 >= 0.f && x0 <= 63.f) ? 1.f : 0.f;
        float vx1 = (x1 >= 0.f && x1 <= 63.f) ? 1.f : 0.f;

        int iy0 = (int)fminf(fmaxf(y0, 0.f), 63.f);
        int iy1 = (int)fminf(fmaxf(y1, 0.f), 63.f);
        int ix0 = (int)fminf(fmaxf(x0, 0.f), 63.f);
        int ix1 = (int)fminf(fmaxf(x1, 0.f), 63.f);

        s_w[k][0][wo] = hh * hw * m * vy0 * vx0;  s_idx[k][0][wo] = iy0 * 64 + ix0;
        s_w[k][1][wo] = hh * lw * m * vy0 * vx1;  s_idx[k][1][wo] = iy0 * 64 + ix1;
        s_w[k][2][wo] = lh * hw * m * vy1 * vx0;  s_idx[k][2][wo] = iy1 * 64 + ix0;
        s_w[k][3][wo] = lh * lw * m * vy1 * vx1;  s_idx[k][3][wo] = iy1 * 64 + ix1;
    }
    __syncthreads();

    const int wo = tid & 63;
    const int cq = tid >> 6;
    const int pg   = (n << 12) + (ho << 6) + wo;   // global pixel
    const int tile = pg >> 7;
    const int pl   = pg & 127;
    const float* xnn = x + (((size_t)(n * C_IN) + half * 128 + cq) << 12);
    char* tbase = (char*)g_colA + (size_t)tile * NCHK * 8192;

    #pragma unroll
    for (int k = 0; k < K2; k++) {
        float w0 = s_w[k][0][wo], w1 = s_w[k][1][wo];
        float w2 = s_w[k][2][wo], w3 = s_w[k][3][wo];
        int i0 = s_idx[k][0][wo], i1 = s_idx[k][1][wo];
        int i2 = s_idx[k][2][wo], i3 = s_idx[k][3][wo];
        const float* xb = xnn;
        #pragma unroll 4
        for (int ci = 0; ci < 32; ci++) {
            int c = half * 128 + ci * 4 + cq;
            int ch = k * 8 + (c >> 5);
            int kcl = c & 31;
            float v = w0 * xb[i0] + w1 * xb[i1] + w2 * xb[i2] + w3 * xb[i3];
            *(__half*)(tbase + (size_t)ch * 8192 + swzA(kcl * 256 + pl * 2))
                = __float2half_rn(v);
            xb += 4 * HW;
        }
    }
}

// ---------------------------------------------------------------------------
// fp16 mma GEMM: contiguous bulk staging (A 8KB + B 16KB per chunk), 4 stages.
// ---------------------------------------------------------------------------
#define A_TILE   8192
#define B_TILE   16384
#define STAGE_SZ (A_TILE + B_TILE)       // 24576
#define NSTAGE   4
#define MBAR_OFF (NSTAGE * STAGE_SZ)     // 98304
#define GEMM_SMEM (MBAR_OFF + 128)
#define STAGE_BYTES STAGE_SZ

__device__ __forceinline__ void bulk_g2s(uint32_t dst, const void* src,
                                         uint32_t bytes, uint32_t mbar) {
    asm volatile(
        "cp.async.bulk.shared::cluster.global.mbarrier::complete_tx::bytes "
        "[%0], [%1], %2, [%3];"
        :: "r"(dst), "l"(src), "r"(bytes), "r"(mbar) : "memory");
}
__device__ __forceinline__ void mbar_init(uint32_t a, uint32_t c) {
    asm volatile("mbarrier.init.shared.b64 [%0], %1;" :: "r"(a), "r"(c) : "memory");
}
__device__ __forceinline__ void mbar_expect(uint32_t a, uint32_t b) {
    asm volatile("mbarrier.arrive.expect_tx.shared.b64 _, [%0], %1;" :: "r"(a), "r"(b) : "memory");
}
__device__ __forceinline__ void mbar_arrive(uint32_t a) {
    asm volatile("mbarrier.arrive.shared.b64 _, [%0];" :: "r"(a) : "memory");
}
__device__ __forceinline__ void mbar_wait(uint32_t mbar, uint32_t parity) {
    uint32_t done;
    asm volatile("{\n\t.reg .pred p;\n\t"
        "mbarrier.try_wait.parity.acquire.cta.shared::cta.b64 p, [%1], %2;\n\t"
        "selp.b32 %0, 1, 0, p;\n\t}"
        : "=r"(done) : "r"(mbar), "r"(parity) : "memory");
    if (!done) {
        asm volatile("{\n\t.reg .pred P1;\n\t"
            "W_%=:\n\t"
            "mbarrier.try_wait.parity.acquire.cta.shared::cta.b64 P1, [%0], %1, 0x989680;\n\t"
            "@P1 bra.uni D_%=;\n\t"
            "bra.uni W_%=;\n\t"
            "D_%=:\n\t}" :: "r"(mbar), "r"(parity) : "memory");
    }
}

__global__ void __launch_bounds__(512, 1) gemm_bulk_kernel(float* __restrict__ out)
{
    extern __shared__ char sm[];
    const uint32_t sb = (uint32_t)__cvta_generic_to_shared(sm);
    const int tid = threadIdx.x;
    const int wid = tid >> 5, lid = tid & 31;
    const int warpM = wid & 3, warpN = wid >> 2;
    const int bm0 = blockIdx.x * 128;
    const int tile = blockIdx.x;

    if (tid == 0) {
        #pragma unroll
        for (int s = 0; s < NSTAGE; s++) {
            mbar_init(sb + MBAR_OFF + s*16, 1);
            mbar_init(sb + MBAR_OFF + s*16 + 8, 512);
        }
    }
    __syncthreads();

    float acc[2][8][4];
    #pragma unroll
    for (int i = 0; i < 2; i++)
        #pragma unroll
        for (int j = 0; j < 8; j++)
            #pragma unroll
            for (int q = 0; q < 4; q++) acc[i][j][q] = 0.f;

    const char* aSrc = (const char*)g_colA + (size_t)tile * NCHK * 8192;

    auto fill = [&](int f) {
        int s = f % NSTAGE;
        uint32_t base = sb + s * STAGE_SZ;
        uint32_t mb   = sb + MBAR_OFF + s * 16;
        mbar_expect(mb, STAGE_BYTES);
        bulk_g2s(base, aSrc + (size_t)f * 8192, A_TILE, mb);
        bulk_g2s(base + A_TILE, g_wtB + (size_t)f * 8192, B_TILE, mb);
    };

    if (tid == 0) {
        #pragma unroll
        for (int f = 0; f < NSTAGE - 1; f++) fill(f);
    }

    const int qq = lid >> 3;
    const int jr = lid & 7;
    // A: pitch 256, swizzled; rel offset before swizzle
    const uint32_t aoff = (uint32_t)(((qq >> 1) * 8 + jr) * 256
                                     + (warpM * 32 + (qq & 1) * 8) * 2);
    const int oc_lane = warpN * 64 + (qq >> 1) * 8 + jr;

    for (int ch = 0; ch < NCHK; ch++) {
        if (tid == 0) {
            int f = ch + NSTAGE - 1;
            if (f < NCHK) {
                if (f >= NSTAGE)
                    mbar_wait(sb + MBAR_OFF + (f % NSTAGE) * 16 + 8,
                              ((f / NSTAGE) - 1) & 1);
                fill(f);
            }
        }
        const int s = ch % NSTAGE;
        mbar_wait(sb + MBAR_OFF + s * 16, (ch / NSTAGE) & 1);

        const uint32_t ab = sb + s * STAGE_SZ;
        const uint32_t bb = ab + A_TILE;

        #pragma unroll
        for (int kp = 0; kp < 2; kp++) {
            uint32_t Af[2][4], Bf[4][4];
            #pragma unroll
            for (int mi = 0; mi < 2; mi++)
                ldmx4t(Af[mi], ab + swzA(aoff + kp * (16 * 256) + mi * 32));
            #pragma unroll
            for (int pi = 0; pi < 4; pi++) {
                uint32_t raw = (uint32_t)(oc_lane + pi * 16) * 64
                             + (kp * 2 + (qq & 1)) * 16;
                ldmx4(Bf[pi], bb + swz64(raw));
            }
            #pragma unroll
            for (int mi = 0; mi < 2; mi++)
                #pragma unroll
                for (int pi = 0; pi < 4; pi++) {
                    mma_f16(acc[mi][pi*2],   Af[mi], &Bf[pi][0]);
                    mma_f16(acc[mi][pi*2+1], Af[mi], &Bf[pi][2]);
                }
        }
        mbar_arrive(sb + MBAR_OFF + s * 16 + 8);
    }

    const int nIdx = bm0 >> 12;
    const int hwb  = bm0 & 4095;
    #pragma unroll
    for (int mi = 0; mi < 2; mi++) {
        int r = hwb + warpM * 32 + mi * 16 + (lid >> 2);
        #pragma unroll
        for (int jj = 0; jj < 8; jj++) {
            int oc = warpN * 64 + jj * 8 + (lid & 3) * 2;
            size_t base = ((size_t)(nIdx * OC + oc) << 12);
            out[base + r]            = acc[mi][jj][0];
            out[base + 4096 + r]     = acc[mi][jj][1];
            out[base + r + 8]        = acc[mi][jj][2];
            out[base + 4096 + r + 8] = acc[mi][jj][3];
        }
    }
}

// ---------------------------------------------------------------------------
extern "C" void kernel_launch(void* const* d_in, const int* in_sizes, int n_in,
                              void* d_out, int out_size)
{
    const float* x  = (const float*)d_in[0];
    const float* ow = (const float*)d_in[1];
    const float* ob = (const float*)d_in[2];
    const float* dw = (const float*)d_in[3];
    float* out = (float*)d_out;

    cudaFuncSetAttribute(gemm_bulk_kernel,
        cudaFuncAttributeMaxDynamicSharedMemorySize, GEMM_SMEM);

    prep_kernel<<<256 + NCHK, 256>>>(dw, ow);
    conv_gemm_kernel<<<NPIX/128, 256>>>(x, ob);
    sample_kernel<<<dim3(H_IM, N_B, 2), 256>>>(x);
    gemm_bulk_kernel<<<NPIX/128, 512, GEMM_SMEM>>>(out);
}